// round 6
// baseline (speedup 1.0000x reference)
#include <cuda_runtime.h>
#include <math.h>

#define B_  16
#define S_  8
#define H_  2048
#define NH_ 16
#define HD_ 128
#define ML_ 4104          // MAX_LEN
#define NSPLIT 8
#define ROWS_PER_WARP 65  // 64 warp-partitions * 65 >= 4104
#define FULLMASK 0xffffffffu

// Scratch (__device__ globals; no allocations allowed)
__device__ float g_q[B_ * NH_ * S_ * HD_];                 // q [bh][s][d], pre-scaled
__device__ float g_attn[B_ * S_ * H_];                     // attn out [b*s][h*128+d]
__device__ float g_part[B_ * NH_ * NSPLIT * S_ * HD_];     // partial O (unnormalized)
__device__ float g_l[B_ * NH_ * NSPLIT * S_];              // partial sum(exp)
__device__ float g_qkvp[4 * 128 * 6144];                   // qkv split-K partials
__device__ float g_projp[8 * 128 * 2048];                  // proj split-K partials

// ---------------------------------------------------------------------------
// GEMM1: qkv partials.  [128,6144] = x[128,2048] @ in_w^T, split-K 4 on z.
// ---------------------------------------------------------------------------
__global__ __launch_bounds__(256)
void qkv_gemm_kernel(const float* __restrict__ x, const float* __restrict__ w)
{
    __shared__ float As[32][64];
    __shared__ float Bs[32][64];
    const int t  = threadIdx.x;
    const int m0 = blockIdx.y * 64, n0 = blockIdx.x * 64;
    const int kbase = blockIdx.z * 512;
    const int tx = t & 15, ty = t >> 4;
    const int lr = t >> 2, lc = (t & 3) << 2;
    float acc[4][4] = {};
    const float* xp = x + (size_t)(m0 + lr) * 2048 + kbase + lc;
    const float* wp = w + (size_t)(n0 + lr) * 2048 + kbase + lc;
    for (int k0 = 0; k0 < 512; k0 += 32) {
        float4 a0 = *(const float4*)(xp + k0);
        float4 a1 = *(const float4*)(xp + k0 + 16);
        float4 b0 = *(const float4*)(wp + k0);
        float4 b1 = *(const float4*)(wp + k0 + 16);
        __syncthreads();
        As[lc+0][lr] = a0.x; As[lc+1][lr] = a0.y; As[lc+2][lr] = a0.z; As[lc+3][lr] = a0.w;
        As[lc+16][lr] = a1.x; As[lc+17][lr] = a1.y; As[lc+18][lr] = a1.z; As[lc+19][lr] = a1.w;
        Bs[lc+0][lr] = b0.x; Bs[lc+1][lr] = b0.y; Bs[lc+2][lr] = b0.z; Bs[lc+3][lr] = b0.w;
        Bs[lc+16][lr] = b1.x; Bs[lc+17][lr] = b1.y; Bs[lc+18][lr] = b1.z; Bs[lc+19][lr] = b1.w;
        __syncthreads();
        #pragma unroll
        for (int kk = 0; kk < 32; kk++) {
            float4 a4 = *(const float4*)&As[kk][ty << 2];
            float4 b4 = *(const float4*)&Bs[kk][tx << 2];
            float av[4] = {a4.x, a4.y, a4.z, a4.w};
            float bv[4] = {b4.x, b4.y, b4.z, b4.w};
            #pragma unroll
            for (int i = 0; i < 4; i++)
                #pragma unroll
                for (int j = 0; j < 4; j++)
                    acc[i][j] = fmaf(av[i], bv[j], acc[i][j]);
        }
    }
    float* dst = g_qkvp + (size_t)blockIdx.z * 128 * 6144;
    #pragma unroll
    for (int i = 0; i < 4; i++) {
        int m = m0 + (ty << 2) + i;
        #pragma unroll
        for (int j = 0; j < 4; j++) {
            int n = n0 + (tx << 2) + j;
            dst[(size_t)m * 6144 + n] = acc[i][j];
        }
    }
}

// Combine qkv partials + bias; q gets pre-scaled by 1/sqrt(HD) into g_q.
__global__ __launch_bounds__(256)
void qkv_combine_kernel(const float* __restrict__ bias, const int* __restrict__ cpp,
                        float* __restrict__ out_k, float* __restrict__ out_v)
{
    int idx = blockIdx.x * 256 + threadIdx.x;       // float4 idx, 196608 total
    int m = idx / 1536, n = (idx % 1536) << 2;
    float4 r = *(const float4*)&bias[n];
    #pragma unroll
    for (int z = 0; z < 4; z++) {
        float4 p = *(const float4*)&g_qkvp[(size_t)z * 128 * 6144 + (size_t)m * 6144 + n];
        r.x += p.x; r.y += p.y; r.z += p.z; r.w += p.w;
    }
    const int cp = *cpp;
    int bb = m >> 3, s = m & 7;
    if (n < 2048) {
        const float scale = 0.08838834764831845f;   // 1/sqrt(128)
        int h = n >> 7, d = n & 127;
        *(float4*)&g_q[(size_t)(((bb << 4) + h) * 8 + s) * 128 + d] =
            make_float4(r.x * scale, r.y * scale, r.z * scale, r.w * scale);
    } else if (n < 4096) {
        int c = n - 2048, h = c >> 7, d = c & 127;
        *(float4*)&out_k[((size_t)((bb << 4) + h) * ML_ + cp + s) * 128 + d] = r;
    } else {
        int c = n - 4096, h = c >> 7, d = c & 127;
        *(float4*)&out_v[((size_t)((bb << 4) + h) * ML_ + cp + s) * 128 + d] = r;
    }
}

// ---------------------------------------------------------------------------
// Fused cache-copy + attention. Warp-independent partitions, no smem/syncs in
// the main loop. BRANCH-FREE copy-loads: source pointer chosen by predicated
// select, unconditional LDG+STG -> ptxas front-batches 8 LDG.128 (MLP~8).
// Streaming cache hints (touch-once data). Folded warp reduction (9 SHFL),
// 1 MUFU exp/row, 8 broadcast SHFL feed PV. exp without max-subtraction.
// ---------------------------------------------------------------------------
__device__ __forceinline__
float4 ld_copy(const float4* __restrict__ in4, float4* __restrict__ out4,
               int p, int cp, int valid, int lane)
{
    size_t off = (size_t)p * 32 + lane;
    // fresh rows [cp,valid) were written by qkv_combine into out4; others come
    // from in4. Branch-free: select source pointer, load, store-back always.
    const float4* src = (p >= cp && p < valid) ? (const float4*)out4 : in4;
    float4 v = __ldcs(&src[off]);
    __stcs(&out4[off], v);
    return v;
}

__global__ __launch_bounds__(256, 2)
void attn_kernel(const float* __restrict__ k_in, const float* __restrict__ v_in,
                 const int* __restrict__ cpp,
                 float* __restrict__ k_out, float* __restrict__ v_out)
{
    const int t     = threadIdx.x;
    const int lane  = t & 31;
    const int w     = t >> 5;
    const int bh    = blockIdx.x;
    const int split = blockIdx.y;
    const int cp    = *cpp;
    const int valid = cp + S_;

    const float4* kin4  = (const float4*)k_in + (size_t)bh * ML_ * 32;
    const float4* vin4  = (const float4*)v_in + (size_t)bh * ML_ * 32;
    float4*       kout4 = (float4*)k_out + (size_t)bh * ML_ * 32;
    float4*       vout4 = (float4*)v_out + (size_t)bh * ML_ * 32;

    // q (pre-scaled): lane owns its float4 slice of all 8 query rows
    float4 q4[8];
    {
        const float4* qp = (const float4*)g_q + (size_t)bh * 256;
        #pragma unroll
        for (int q = 0; q < 8; q++) q4[q] = qp[q * 32 + lane];
    }

    float4 acc[8];
    #pragma unroll
    for (int q = 0; q < 8; q++) acc[q] = make_float4(0.f, 0.f, 0.f, 0.f);
    float l_dist = 0.f;                 // sum(exp) for query (lane>>2)&7

    const int wi = (split << 3) + w;                 // 0..63
    const int r0 = wi * ROWS_PER_WARP;
    const int r1 = min(r0 + ROWS_PER_WARP, ML_);

    const bool hi16 = (lane & 16) != 0;
    const bool hi8  = (lane & 8) != 0;
    const bool hi4  = (lane & 4) != 0;

    for (int p0 = r0; p0 < r1; p0 += 4) {
        const int nr = min(4, r1 - p0);

        // ---- batched branch-free loads (+ copy): MLP ~8 ----
        float4 kk[4], vv[4];
        #pragma unroll
        for (int i = 0; i < 4; i++)
            if (i < nr) kk[i] = ld_copy(kin4, kout4, p0 + i, cp, valid, lane);
        #pragma unroll
        for (int i = 0; i < 4; i++)
            if (i < nr) vv[i] = ld_copy(vin4, vout4, p0 + i, cp, valid, lane);

        // ---- per-row: dots, folded reduce, exp, accumulate ----
        #pragma unroll
        for (int i = 0; i < 4; i++) {
            if (i >= nr) break;
            float s[8];
            #pragma unroll
            for (int q = 0; q < 8; q++)
                s[q] = fmaf(q4[q].x, kk[i].x, fmaf(q4[q].y, kk[i].y,
                       fmaf(q4[q].z, kk[i].z, q4[q].w * kk[i].w)));

            if (p0 + i < valid) {                     // warp-uniform
                // fold: 8 values -> 1 per lane; query q ends in lanes 4q..4q+3
                #pragma unroll
                for (int j = 0; j < 4; j++) {
                    float send = hi16 ? s[j] : s[j + 4];
                    float recv = __shfl_xor_sync(FULLMASK, send, 16);
                    s[j] = (hi16 ? s[j + 4] : s[j]) + recv;
                }
                #pragma unroll
                for (int j = 0; j < 2; j++) {
                    float send = hi8 ? s[j] : s[j + 2];
                    float recv = __shfl_xor_sync(FULLMASK, send, 8);
                    s[j] = (hi8 ? s[j + 2] : s[j]) + recv;
                }
                {
                    float send = hi4 ? s[0] : s[1];
                    float recv = __shfl_xor_sync(FULLMASK, send, 4);
                    s[0] = (hi4 ? s[1] : s[0]) + recv;
                }
                s[0] += __shfl_xor_sync(FULLMASK, s[0], 2);
                s[0] += __shfl_xor_sync(FULLMASK, s[0], 1);

                float p = __expf(s[0]);               // 1 MUFU/row
                l_dist += p;

                float4 v4 = vv[i];
                #pragma unroll
                for (int q = 0; q < 8; q++) {
                    float pq = __shfl_sync(FULLMASK, p, q << 2);
                    acc[q].x = fmaf(pq, v4.x, acc[q].x);
                    acc[q].y = fmaf(pq, v4.y, acc[q].y);
                    acc[q].z = fmaf(pq, v4.z, acc[q].z);
                    acc[q].w = fmaf(pq, v4.w, acc[q].w);
                }
            }
        }
    }

    // ---- one block-level reduction at the very end ----
    __shared__ float4 red[8 * 8 * 32];   // [warp][query][lane] 32KB
    __shared__ float  lred[8][8];
    #pragma unroll
    for (int q = 0; q < 8; q++)
        red[(w << 8) + (q << 5) + lane] = acc[q];
    if ((lane & 3) == 0) lred[w][lane >> 2] = l_dist;
    __syncthreads();

    const int qq = w;
    float4 o = make_float4(0.f, 0.f, 0.f, 0.f);
    #pragma unroll
    for (int ww = 0; ww < 8; ww++) {
        float4 p = red[(ww << 8) + (qq << 5) + lane];
        o.x += p.x; o.y += p.y; o.z += p.z; o.w += p.w;
    }
    ((float4*)g_part)[(((size_t)bh * NSPLIT + split) * 8 + qq) * 32 + lane] = o;
    if (lane == 0) {
        float L = 0.f;
        #pragma unroll
        for (int ww = 0; ww < 8; ww++) L += lred[ww][qq];
        g_l[((size_t)bh * NSPLIT + split) * 8 + qq] = L;
    }
}

// Combine split partials (plain sums, no max bookkeeping) -> g_attn
__global__ __launch_bounds__(256)
void attn_combine_kernel()
{
    const int bh = blockIdx.x, t = threadIdx.x;
    const int q = t >> 5, ds = t & 31;
    float4 o = make_float4(0.f, 0.f, 0.f, 0.f);
    float L = 0.f;
    #pragma unroll
    for (int s = 0; s < NSPLIT; s++) {
        float4 p = ((const float4*)g_part)[(((size_t)bh * NSPLIT + s) * 8 + q) * 32 + ds];
        o.x += p.x; o.y += p.y; o.z += p.z; o.w += p.w;
        L += g_l[((size_t)bh * NSPLIT + s) * 8 + q];
    }
    float il = 1.f / L;
    int bb = bh >> 4, h = bh & 15;
    ((float4*)g_attn)[(size_t)(bb * 8 + q) * 512 + h * 32 + ds] =
        make_float4(o.x * il, o.y * il, o.z * il, o.w * il);
}

// ---------------------------------------------------------------------------
// GEMM2: proj partials. [128,2048] = g_attn @ out_w^T, split-K 8 on z.
// ---------------------------------------------------------------------------
__global__ __launch_bounds__(256)
void proj_gemm_kernel(const float* __restrict__ w)
{
    __shared__ float As[32][64];
    __shared__ float Bs[32][64];
    const int t  = threadIdx.x;
    const int m0 = blockIdx.y * 64, n0 = blockIdx.x * 64;
    const int kbase = blockIdx.z * 256;
    const int tx = t & 15, ty = t >> 4;
    const int lr = t >> 2, lc = (t & 3) << 2;
    float acc[4][4] = {};
    const float* xp = g_attn + (size_t)(m0 + lr) * 2048 + kbase + lc;
    const float* wp = w + (size_t)(n0 + lr) * 2048 + kbase + lc;
    for (int k0 = 0; k0 < 256; k0 += 32) {
        float4 a0 = *(const float4*)(xp + k0);
        float4 a1 = *(const float4*)(xp + k0 + 16);
        float4 b0 = *(const float4*)(wp + k0);
        float4 b1 = *(const float4*)(wp + k0 + 16);
        __syncthreads();
        As[lc+0][lr] = a0.x; As[lc+1][lr] = a0.y; As[lc+2][lr] = a0.z; As[lc+3][lr] = a0.w;
        As[lc+16][lr] = a1.x; As[lc+17][lr] = a1.y; As[lc+18][lr] = a1.z; As[lc+19][lr] = a1.w;
        Bs[lc+0][lr] = b0.x; Bs[lc+1][lr] = b0.y; Bs[lc+2][lr] = b0.z; Bs[lc+3][lr] = b0.w;
        Bs[lc+16][lr] = b1.x; Bs[lc+17][lr] = b1.y; Bs[lc+18][lr] = b1.z; Bs[lc+19][lr] = b1.w;
        __syncthreads();
        #pragma unroll
        for (int kk = 0; kk < 32; kk++) {
            float4 a4 = *(const float4*)&As[kk][ty << 2];
            float4 b4 = *(const float4*)&Bs[kk][tx << 2];
            float av[4] = {a4.x, a4.y, a4.z, a4.w};
            float bv[4] = {b4.x, b4.y, b4.z, b4.w};
            #pragma unroll
            for (int i = 0; i < 4; i++)
                #pragma unroll
                for (int j = 0; j < 4; j++)
                    acc[i][j] = fmaf(av[i], bv[j], acc[i][j]);
        }
    }
    float* dst = g_projp + (size_t)blockIdx.z * 128 * 2048;
    #pragma unroll
    for (int i = 0; i < 4; i++) {
        int m = m0 + (ty << 2) + i;
        #pragma unroll
        for (int j = 0; j < 4; j++) {
            int n = n0 + (tx << 2) + j;
            dst[(size_t)m * 2048 + n] = acc[i][j];
        }
    }
}

__global__ __launch_bounds__(256)
void proj_combine_kernel(const float* __restrict__ bias, float* __restrict__ out)
{
    int idx = blockIdx.x * 256 + threadIdx.x;   // float4 idx, 65536 total
    int m = idx >> 9, n = (idx & 511) << 2;
    float4 r = *(const float4*)&bias[n];
    #pragma unroll
    for (int z = 0; z < 8; z++) {
        float4 p = *(const float4*)&g_projp[(size_t)z * 128 * 2048 + (size_t)m * 2048 + n];
        r.x += p.x; r.y += p.y; r.z += p.z; r.w += p.w;
    }
    *(float4*)&out[(size_t)m * 2048 + n] = r;
}

// ---------------------------------------------------------------------------
extern "C" void kernel_launch(void* const* d_in, const int* in_sizes, int n_in,
                              void* d_out, int out_size)
{
    const float* x     = (const float*)d_in[0];
    const float* kc    = (const float*)d_in[1];
    const float* vc    = (const float*)d_in[2];
    const float* in_w  = (const float*)d_in[3];
    const float* in_b  = (const float*)d_in[4];
    const float* out_w = (const float*)d_in[5];
    const float* out_b = (const float*)d_in[6];
    const int*   cpp   = (const int*)d_in[7];

    float* out   = (float*)d_out;                         // [16,8,2048]
    float* out_k = out + (size_t)B_ * S_ * H_;            // [16,16,4104,128]
    float* out_v = out_k + (size_t)B_ * NH_ * ML_ * HD_;  // [16,16,4104,128]

    qkv_gemm_kernel<<<dim3(96, 2, 4), 256>>>(x, in_w);
    qkv_combine_kernel<<<768, 256>>>(in_b, cpp, out_k, out_v);
    attn_kernel<<<dim3(256, NSPLIT), 256>>>(kc, vc, cpp, out_k, out_v);
    attn_combine_kernel<<<256, 256>>>();
    proj_gemm_kernel<<<dim3(32, 2, 8), 256>>>(out_w);
    proj_combine_kernel<<<256, 256>>>(out_b, out);
}

// round 8
// speedup vs baseline: 1.0632x; 1.0632x over previous
#include <cuda_runtime.h>
#include <math.h>

#define B_  16
#define S_  8
#define H_  2048
#define NH_ 16
#define HD_ 128
#define ML_ 4104          // MAX_LEN
#define NSPLIT 8
#define ROWS_PER_WARP 65  // 64 warp-partitions * 65 >= 4104
#define FULLMASK 0xffffffffu

// Scratch (__device__ globals; no allocations allowed)
__device__ float g_q[B_ * NH_ * S_ * HD_];                 // q [bh][s][d], pre-scaled
__device__ float g_attn[B_ * S_ * H_];                     // attn out [b*s][h*128+d]
__device__ float g_part[B_ * NH_ * NSPLIT * S_ * HD_];     // partial O (unnormalized)
__device__ float g_l[B_ * NH_ * NSPLIT * S_];              // partial sum(exp)
__device__ float g_qkvp[4 * 128 * 6144];                   // qkv split-K partials
__device__ float g_projp[8 * 128 * 2048];                  // proj split-K partials

// ---------------------------------------------------------------------------
// GEMM1: qkv partials.  [128,6144] = x[128,2048] @ in_w^T, split-K 4 on z.
// ---------------------------------------------------------------------------
__global__ __launch_bounds__(256)
void qkv_gemm_kernel(const float* __restrict__ x, const float* __restrict__ w)
{
    __shared__ float As[32][64];
    __shared__ float Bs[32][64];
    const int t  = threadIdx.x;
    const int m0 = blockIdx.y * 64, n0 = blockIdx.x * 64;
    const int kbase = blockIdx.z * 512;
    const int tx = t & 15, ty = t >> 4;
    const int lr = t >> 2, lc = (t & 3) << 2;
    float acc[4][4] = {};
    const float* xp = x + (size_t)(m0 + lr) * 2048 + kbase + lc;
    const float* wp = w + (size_t)(n0 + lr) * 2048 + kbase + lc;
    for (int k0 = 0; k0 < 512; k0 += 32) {
        float4 a0 = *(const float4*)(xp + k0);
        float4 a1 = *(const float4*)(xp + k0 + 16);
        float4 b0 = *(const float4*)(wp + k0);
        float4 b1 = *(const float4*)(wp + k0 + 16);
        __syncthreads();
        As[lc+0][lr] = a0.x; As[lc+1][lr] = a0.y; As[lc+2][lr] = a0.z; As[lc+3][lr] = a0.w;
        As[lc+16][lr] = a1.x; As[lc+17][lr] = a1.y; As[lc+18][lr] = a1.z; As[lc+19][lr] = a1.w;
        Bs[lc+0][lr] = b0.x; Bs[lc+1][lr] = b0.y; Bs[lc+2][lr] = b0.z; Bs[lc+3][lr] = b0.w;
        Bs[lc+16][lr] = b1.x; Bs[lc+17][lr] = b1.y; Bs[lc+18][lr] = b1.z; Bs[lc+19][lr] = b1.w;
        __syncthreads();
        #pragma unroll
        for (int kk = 0; kk < 32; kk++) {
            float4 a4 = *(const float4*)&As[kk][ty << 2];
            float4 b4 = *(const float4*)&Bs[kk][tx << 2];
            float av[4] = {a4.x, a4.y, a4.z, a4.w};
            float bv[4] = {b4.x, b4.y, b4.z, b4.w};
            #pragma unroll
            for (int i = 0; i < 4; i++)
                #pragma unroll
                for (int j = 0; j < 4; j++)
                    acc[i][j] = fmaf(av[i], bv[j], acc[i][j]);
        }
    }
    float* dst = g_qkvp + (size_t)blockIdx.z * 128 * 6144;
    #pragma unroll
    for (int i = 0; i < 4; i++) {
        int m = m0 + (ty << 2) + i;
        #pragma unroll
        for (int j = 0; j < 4; j++) {
            int n = n0 + (tx << 2) + j;
            dst[(size_t)m * 6144 + n] = acc[i][j];
        }
    }
}

// Combine qkv partials + bias; q gets pre-scaled by 1/sqrt(HD) into g_q.
__global__ __launch_bounds__(256)
void qkv_combine_kernel(const float* __restrict__ bias, const int* __restrict__ cpp,
                        float* __restrict__ out_k, float* __restrict__ out_v)
{
    int idx = blockIdx.x * 256 + threadIdx.x;       // float4 idx, 196608 total
    int m = idx / 1536, n = (idx % 1536) << 2;
    float4 r = *(const float4*)&bias[n];
    #pragma unroll
    for (int z = 0; z < 4; z++) {
        float4 p = *(const float4*)&g_qkvp[(size_t)z * 128 * 6144 + (size_t)m * 6144 + n];
        r.x += p.x; r.y += p.y; r.z += p.z; r.w += p.w;
    }
    const int cp = *cpp;
    int bb = m >> 3, s = m & 7;
    if (n < 2048) {
        const float scale = 0.08838834764831845f;   // 1/sqrt(128)
        int h = n >> 7, d = n & 127;
        *(float4*)&g_q[(size_t)(((bb << 4) + h) * 8 + s) * 128 + d] =
            make_float4(r.x * scale, r.y * scale, r.z * scale, r.w * scale);
    } else if (n < 4096) {
        int c = n - 2048, h = c >> 7, d = c & 127;
        *(float4*)&out_k[((size_t)((bb << 4) + h) * ML_ + cp + s) * 128 + d] = r;
    } else {
        int c = n - 4096, h = c >> 7, d = c & 127;
        *(float4*)&out_v[((size_t)((bb << 4) + h) * ML_ + cp + s) * 128 + d] = r;
    }
}

// No-op spacer so attn_kernel lands in the ncu capture slot (4th launch).
__global__ void noop_kernel() {}

// ---------------------------------------------------------------------------
// Fused cache-copy + attention. Warp-independent partitions, no smem/syncs in
// the main loop. SINGLE kv[4] register buffer: K loads batched; per-row the
// dot consumes kv[i], the V load immediately reuses kv[i] (issued before the
// fold/exp chain -> latency overlap), PV runs after all folds.
// Probability mask: p0+i < min(r1, valid) -- rows outside the partition
// (nr<4 tail) and masked positions contribute exactly zero.
// ---------------------------------------------------------------------------
__device__ __forceinline__
float4 ld_copy(const float4* __restrict__ in4, float4* __restrict__ out4,
               int p, int cp, int valid, int lane)
{
    size_t off = (size_t)p * 32 + lane;
    const float4* src = (p >= cp && p < valid) ? (const float4*)out4 : in4;
    float4 v = __ldcs(&src[off]);
    __stcs(&out4[off], v);
    return v;
}

__global__ __launch_bounds__(256, 2)
void attn_kernel(const float* __restrict__ k_in, const float* __restrict__ v_in,
                 const int* __restrict__ cpp,
                 float* __restrict__ k_out, float* __restrict__ v_out)
{
    const int t     = threadIdx.x;
    const int lane  = t & 31;
    const int w     = t >> 5;
    const int bh    = blockIdx.x;
    const int split = blockIdx.y;
    const int cp    = *cpp;
    const int valid = cp + S_;

    const float4* kin4  = (const float4*)k_in + (size_t)bh * ML_ * 32;
    const float4* vin4  = (const float4*)v_in + (size_t)bh * ML_ * 32;
    float4*       kout4 = (float4*)k_out + (size_t)bh * ML_ * 32;
    float4*       vout4 = (float4*)v_out + (size_t)bh * ML_ * 32;

    // q (pre-scaled): lane owns its float4 slice of all 8 query rows
    float4 q4[8];
    {
        const float4* qp = (const float4*)g_q + (size_t)bh * 256;
        #pragma unroll
        for (int q = 0; q < 8; q++) q4[q] = qp[q * 32 + lane];
    }

    float4 acc[8];
    #pragma unroll
    for (int q = 0; q < 8; q++) acc[q] = make_float4(0.f, 0.f, 0.f, 0.f);
    float l_dist = 0.f;                 // sum(exp) for query lane>>2

    const int wi = (split << 3) + w;                 // 0..63
    const int r0 = wi * ROWS_PER_WARP;
    const int r1 = min(r0 + ROWS_PER_WARP, ML_);
    const int lim = min(r1, valid);     // rows that contribute probability mass

    const bool hi16 = (lane & 16) != 0;
    const bool hi8  = (lane & 8) != 0;
    const bool hi4  = (lane & 4) != 0;

    for (int p0 = r0; p0 < r1; p0 += 4) {
        const int nr = min(4, r1 - p0);

        // ---- K loads (+copy), batched: MLP 4 ----
        float4 kv[4];
        #pragma unroll
        for (int i = 0; i < 4; i++)
            kv[i] = (i < nr) ? ld_copy(kin4, kout4, p0 + i, cp, valid, lane)
                             : make_float4(0.f, 0.f, 0.f, 0.f);

        float pr[4];
        #pragma unroll
        for (int i = 0; i < 4; i++) {
            // dot: consumes kv[i]
            float s[8];
            #pragma unroll
            for (int q = 0; q < 8; q++)
                s[q] = fmaf(q4[q].x, kv[i].x, fmaf(q4[q].y, kv[i].y,
                       fmaf(q4[q].z, kv[i].z, q4[q].w * kv[i].w)));

            // V load reuses kv[i]'s registers; issued before the fold chain
            kv[i] = (i < nr) ? ld_copy(vin4, vout4, p0 + i, cp, valid, lane)
                             : make_float4(0.f, 0.f, 0.f, 0.f);

            // fold: 8 values -> 1 per lane; query (lane>>2) sum in every lane
            #pragma unroll
            for (int j = 0; j < 4; j++) {
                float send = hi16 ? s[j] : s[j + 4];
                float recv = __shfl_xor_sync(FULLMASK, send, 16);
                s[j] = (hi16 ? s[j + 4] : s[j]) + recv;
            }
            #pragma unroll
            for (int j = 0; j < 2; j++) {
                float send = hi8 ? s[j] : s[j + 2];
                float recv = __shfl_xor_sync(FULLMASK, send, 8);
                s[j] = (hi8 ? s[j + 2] : s[j]) + recv;
            }
            {
                float send = hi4 ? s[0] : s[1];
                float recv = __shfl_xor_sync(FULLMASK, send, 4);
                s[0] = (hi4 ? s[1] : s[0]) + recv;
            }
            s[0] += __shfl_xor_sync(FULLMASK, s[0], 2);
            s[0] += __shfl_xor_sync(FULLMASK, s[0], 1);

            pr[i] = (p0 + i < lim) ? __expf(s[0]) : 0.f;   // masked rows: 0
            l_dist += pr[i];
        }

        // ---- PV: kv now holds V rows; pr broadcast via SHFL ----
        #pragma unroll
        for (int i = 0; i < 4; i++) {
            float4 v4 = kv[i];
            #pragma unroll
            for (int q = 0; q < 8; q++) {
                float pq = __shfl_sync(FULLMASK, pr[i], q << 2);
                acc[q].x = fmaf(pq, v4.x, acc[q].x);
                acc[q].y = fmaf(pq, v4.y, acc[q].y);
                acc[q].z = fmaf(pq, v4.z, acc[q].z);
                acc[q].w = fmaf(pq, v4.w, acc[q].w);
            }
        }
    }

    // ---- one block-level reduction at the very end ----
    __shared__ float4 red[8 * 8 * 32];   // [warp][query][lane] 32KB
    __shared__ float  lred[8][8];
    #pragma unroll
    for (int q = 0; q < 8; q++)
        red[(w << 8) + (q << 5) + lane] = acc[q];
    if ((lane & 3) == 0) lred[w][lane >> 2] = l_dist;
    __syncthreads();

    const int qq = w;
    float4 o = make_float4(0.f, 0.f, 0.f, 0.f);
    #pragma unroll
    for (int ww = 0; ww < 8; ww++) {
        float4 p = red[(ww << 8) + (qq << 5) + lane];
        o.x += p.x; o.y += p.y; o.z += p.z; o.w += p.w;
    }
    ((float4*)g_part)[(((size_t)bh * NSPLIT + split) * 8 + qq) * 32 + lane] = o;
    if (lane == 0) {
        float L = 0.f;
        #pragma unroll
        for (int ww = 0; ww < 8; ww++) L += lred[ww][qq];
        g_l[((size_t)bh * NSPLIT + split) * 8 + qq] = L;
    }
}

// Combine split partials (plain sums, no max bookkeeping) -> g_attn
__global__ __launch_bounds__(256)
void attn_combine_kernel()
{
    const int bh = blockIdx.x, t = threadIdx.x;
    const int q = t >> 5, ds = t & 31;
    float4 o = make_float4(0.f, 0.f, 0.f, 0.f);
    float L = 0.f;
    #pragma unroll
    for (int s = 0; s < NSPLIT; s++) {
        float4 p = ((const float4*)g_part)[(((size_t)bh * NSPLIT + s) * 8 + q) * 32 + ds];
        o.x += p.x; o.y += p.y; o.z += p.z; o.w += p.w;
        L += g_l[((size_t)bh * NSPLIT + s) * 8 + q];
    }
    float il = 1.f / L;
    int bb = bh >> 4, h = bh & 15;
    ((float4*)g_attn)[(size_t)(bb * 8 + q) * 512 + h * 32 + ds] =
        make_float4(o.x * il, o.y * il, o.z * il, o.w * il);
}

// ---------------------------------------------------------------------------
// GEMM2: proj partials. [128,2048] = g_attn @ out_w^T, split-K 8 on z.
// ---------------------------------------------------------------------------
__global__ __launch_bounds__(256)
void proj_gemm_kernel(const float* __restrict__ w)
{
    __shared__ float As[32][64];
    __shared__ float Bs[32][64];
    const int t  = threadIdx.x;
    const int m0 = blockIdx.y * 64, n0 = blockIdx.x * 64;
    const int kbase = blockIdx.z * 256;
    const int tx = t & 15, ty = t >> 4;
    const int lr = t >> 2, lc = (t & 3) << 2;
    float acc[4][4] = {};
    const float* xp = g_attn + (size_t)(m0 + lr) * 2048 + kbase + lc;
    const float* wp = w + (size_t)(n0 + lr) * 2048 + kbase + lc;
    for (int k0 = 0; k0 < 256; k0 += 32) {
        float4 a0 = *(const float4*)(xp + k0);
        float4 a1 = *(const float4*)(xp + k0 + 16);
        float4 b0 = *(const float4*)(wp + k0);
        float4 b1 = *(const float4*)(wp + k0 + 16);
        __syncthreads();
        As[lc+0][lr] = a0.x; As[lc+1][lr] = a0.y; As[lc+2][lr] = a0.z; As[lc+3][lr] = a0.w;
        As[lc+16][lr] = a1.x; As[lc+17][lr] = a1.y; As[lc+18][lr] = a1.z; As[lc+19][lr] = a1.w;
        Bs[lc+0][lr] = b0.x; Bs[lc+1][lr] = b0.y; Bs[lc+2][lr] = b0.z; Bs[lc+3][lr] = b0.w;
        Bs[lc+16][lr] = b1.x; Bs[lc+17][lr] = b1.y; Bs[lc+18][lr] = b1.z; Bs[lc+19][lr] = b1.w;
        __syncthreads();
        #pragma unroll
        for (int kk = 0; kk < 32; kk++) {
            float4 a4 = *(const float4*)&As[kk][ty << 2];
            float4 b4 = *(const float4*)&Bs[kk][tx << 2];
            float av[4] = {a4.x, a4.y, a4.z, a4.w};
            float bv[4] = {b4.x, b4.y, b4.z, b4.w};
            #pragma unroll
            for (int i = 0; i < 4; i++)
                #pragma unroll
                for (int j = 0; j < 4; j++)
                    acc[i][j] = fmaf(av[i], bv[j], acc[i][j]);
        }
    }
    float* dst = g_projp + (size_t)blockIdx.z * 128 * 2048;
    #pragma unroll
    for (int i = 0; i < 4; i++) {
        int m = m0 + (ty << 2) + i;
        #pragma unroll
        for (int j = 0; j < 4; j++) {
            int n = n0 + (tx << 2) + j;
            dst[(size_t)m * 2048 + n] = acc[i][j];
        }
    }
}

__global__ __launch_bounds__(256)
void proj_combine_kernel(const float* __restrict__ bias, float* __restrict__ out)
{
    int idx = blockIdx.x * 256 + threadIdx.x;   // float4 idx, 65536 total
    int m = idx >> 9, n = (idx & 511) << 2;
    float4 r = *(const float4*)&bias[n];
    #pragma unroll
    for (int z = 0; z < 8; z++) {
        float4 p = *(const float4*)&g_projp[(size_t)z * 128 * 2048 + (size_t)m * 2048 + n];
        r.x += p.x; r.y += p.y; r.z += p.z; r.w += p.w;
    }
    *(float4*)&out[(size_t)m * 2048 + n] = r;
}

// ---------------------------------------------------------------------------
extern "C" void kernel_launch(void* const* d_in, const int* in_sizes, int n_in,
                              void* d_out, int out_size)
{
    const float* x     = (const float*)d_in[0];
    const float* kc    = (const float*)d_in[1];
    const float* vc    = (const float*)d_in[2];
    const float* in_w  = (const float*)d_in[3];
    const float* in_b  = (const float*)d_in[4];
    const float* out_w = (const float*)d_in[5];
    const float* out_b = (const float*)d_in[6];
    const int*   cpp   = (const int*)d_in[7];

    float* out   = (float*)d_out;                         // [16,8,2048]
    float* out_k = out + (size_t)B_ * S_ * H_;            // [16,16,4104,128]
    float* out_v = out_k + (size_t)B_ * NH_ * ML_ * HD_;  // [16,16,4104,128]

    qkv_gemm_kernel<<<dim3(96, 2, 4), 256>>>(x, in_w);
    qkv_combine_kernel<<<768, 256>>>(in_b, cpp, out_k, out_v);
    noop_kernel<<<1, 32>>>();   // spacer: puts attn_kernel in ncu's capture slot
    attn_kernel<<<dim3(256, NSPLIT), 256>>>(kc, vc, cpp, out_k, out_v);
    attn_combine_kernel<<<256, 256>>>();
    proj_gemm_kernel<<<dim3(32, 2, 8), 256>>>(out_w);
    proj_combine_kernel<<<256, 256>>>(out_b, out);
}